// round 1
// baseline (speedup 1.0000x reference)
#include <cuda_runtime.h>
#include <math.h>

#define N_DATA 100000
#define NP     100096              // padded to 782 * 128
#define N_TILES (NP / 128)
#define D      64
#define BQ     2048
#define HID    256
#define QB     16                  // queries per CTA
#define KNN    20

__device__ float g_dataT[D * NP];  // 25.6 MB transposed data, dim-major
__device__ float g_pp[NP];         // ||p||^2 (1e30 for padding)

// ---------------------------------------------------------------------------
// Transpose data (N,64) -> dataT (64, NP), zero-pad tail points
// ---------------------------------------------------------------------------
__global__ void transpose_k(const float* __restrict__ data) {
    __shared__ float t[32][33];
    int p0 = blockIdx.x * 32, j0 = blockIdx.y * 32;
    for (int r = threadIdx.y; r < 32; r += 8) {
        int p = p0 + r;
        t[r][threadIdx.x] = (p < N_DATA) ? data[p * D + j0 + threadIdx.x] : 0.f;
    }
    __syncthreads();
    for (int r = threadIdx.y; r < 32; r += 8) {
        g_dataT[(j0 + r) * NP + p0 + threadIdx.x] = t[threadIdx.x][r];
    }
}

// ---------------------------------------------------------------------------
// pp[p] = sum_j dataT[j][p]^2  (coalesced over p)
// ---------------------------------------------------------------------------
__global__ void pp_k() {
    int p = blockIdx.x * 256 + threadIdx.x;
    if (p >= NP) return;
    if (p >= N_DATA) { g_pp[p] = 1e30f; return; }
    float s = 0.f;
#pragma unroll
    for (int j = 0; j < D; j++) { float v = g_dataT[j * NP + p]; s += v * v; }
    g_pp[p] = s;
}

// ---------------------------------------------------------------------------
// MLP: x_dot = relu([x,t] @ W1 + b1) @ W2 + b2 ; write into out[:, 0:64]
// ---------------------------------------------------------------------------
__global__ __launch_bounds__(256) void mlp_k(
    const float* __restrict__ t, const float* __restrict__ z,
    const float* __restrict__ W1, const float* __restrict__ b1,
    const float* __restrict__ W2, const float* __restrict__ b2,
    float* __restrict__ out)
{
    __shared__ float sIn[16 * 68];
    __shared__ float sH[16 * 258];
    int tid = threadIdx.x;
    int r0 = blockIdx.x * 16;
    float tv = t[0];
    for (int i = tid; i < 16 * 65; i += 256) {
        int r = i / 65, c = i % 65;
        sIn[r * 68 + c] = (c < 64) ? z[(r0 + r) * 66 + c] : tv;
    }
    __syncthreads();
    {
        int r = tid & 15, jb = tid >> 4;
#pragma unroll
        for (int jj = 0; jj < 16; jj++) {
            int j = jb + jj * 16;
            float acc = b1[j];
#pragma unroll
            for (int i = 0; i < 65; i++) acc += sIn[r * 68 + i] * W1[i * 256 + j];
            sH[r * 258 + j] = fmaxf(acc, 0.f);
        }
    }
    __syncthreads();
    {
        int r = tid >> 4, db = tid & 15;
        int d0 = db * 4;
        float a0 = b2[d0], a1 = b2[d0 + 1], a2 = b2[d0 + 2], a3 = b2[d0 + 3];
#pragma unroll 8
        for (int j = 0; j < 256; j++) {
            float hv = sH[r * 258 + j];
            float4 w = *reinterpret_cast<const float4*>(W2 + j * 64 + d0);
            a0 += hv * w.x; a1 += hv * w.y; a2 += hv * w.z; a3 += hv * w.w;
        }
        int gq = r0 + r;
        out[gq * 66 + d0 + 0] = a0;
        out[gq * 66 + d0 + 1] = a1;
        out[gq * 66 + d0 + 2] = a2;
        out[gq * 66 + d0 + 3] = a3;
    }
}

// ---------------------------------------------------------------------------
// KNN + weighted velocity + metrics. CTA = 256 threads, 16 queries.
// Thread (q = tid>>4, pg = tid&15) handles query q x points [pg*8, pg*8+8)
// of every 128-point tile, keeping a register-resident sorted top-20.
// ---------------------------------------------------------------------------
struct KSmem {
    float sD[64 * 132];     // tile, dim-major, row stride 132 (pad)
    float ppT[128];
    float sQ[64 * 16];      // queries, dim-major
    float qq[16];
    float listD[256 * KNN];
    int   listI[256 * KNN];
    float selW[16 * KNN];
    int   selI[16 * KNN];
    float uS[16 * 68];
};

__global__ __launch_bounds__(256) void knn_k(
    const float* __restrict__ z, const float* __restrict__ velocity,
    float* __restrict__ out)
{
    extern __shared__ char smem_raw[];
    KSmem& s = *reinterpret_cast<KSmem*>(smem_raw);
    int tid = threadIdx.x;
    int q = tid >> 4, pg = tid & 15;
    int q0 = blockIdx.x * QB;

    // load 16 queries (dim-major) + ||q||^2
    for (int i = tid; i < 64 * 16; i += 256) {
        int qq_ = i & 15, j = i >> 4;
        s.sQ[j * 16 + qq_] = z[(q0 + qq_) * 66 + j];
    }
    __syncthreads();
    if (tid < 16) {
        float sum = 0.f;
#pragma unroll
        for (int j = 0; j < 64; j++) { float v = s.sQ[j * 16 + tid]; sum += v * v; }
        s.qq[tid] = sum;
    }
    __syncthreads();
    float qqv = s.qq[q];

    float best[KNN]; int bestI[KNN];
#pragma unroll
    for (int k = 0; k < KNN; k++) { best[k] = 3.4e38f; bestI[k] = 0; }

    for (int tile = 0; tile < N_TILES; tile++) {
        __syncthreads();
        const float* gsrc = g_dataT + tile * 128;
        for (int i = tid; i < 64 * 32; i += 256) {
            int j = i >> 5, p4 = i & 31;
            float4 v = reinterpret_cast<const float4*>(gsrc + j * NP)[p4];
            reinterpret_cast<float4*>(s.sD + j * 132)[p4] = v;
        }
        if (tid < 32)
            reinterpret_cast<float4*>(s.ppT)[tid] =
                reinterpret_cast<const float4*>(g_pp + tile * 128)[tid];
        __syncthreads();

        float acc[8] = {0.f, 0.f, 0.f, 0.f, 0.f, 0.f, 0.f, 0.f};
        const float* qptr = s.sQ + q;
        const float* dbase = s.sD + pg * 8;
#pragma unroll 4
        for (int j = 0; j < 64; j++) {
            float qv = qptr[j * 16];
            float4 a  = *reinterpret_cast<const float4*>(dbase + j * 132);
            float4 b4 = *reinterpret_cast<const float4*>(dbase + j * 132 + 4);
            acc[0] += qv * a.x;  acc[1] += qv * a.y;
            acc[2] += qv * a.z;  acc[3] += qv * a.w;
            acc[4] += qv * b4.x; acc[5] += qv * b4.y;
            acc[6] += qv * b4.z; acc[7] += qv * b4.w;
        }
        int pbase = tile * 128 + pg * 8;
#pragma unroll
        for (int i = 0; i < 8; i++) {
            float sq = qqv + s.ppT[pg * 8 + i] - 2.f * acc[i];
            if (sq < best[KNN - 1]) {
                float cd = sq; int ci = pbase + i;
#pragma unroll
                for (int k = 0; k < KNN; k++) {
                    if (cd < best[k]) {
                        float td = best[k]; best[k] = cd; cd = td;
                        int ti = bestI[k]; bestI[k] = ci; ci = ti;
                    }
                }
            }
        }
    }
    __syncthreads();
#pragma unroll
    for (int k = 0; k < KNN; k++) {
        s.listD[tid * KNN + k] = best[k];
        s.listI[tid * KNN + k] = bestI[k];
    }
    __syncthreads();

    // 16-way merge of sorted lists per query, then weights
    if (tid < 16) {
        int ptr[16];
#pragma unroll
        for (int l = 0; l < 16; l++) ptr[l] = 0;
        for (int o = 0; o < KNN; o++) {
            float bd = 3.5e38f; int bl = 0;
            for (int l = 0; l < 16; l++) {
                if (ptr[l] < KNN) {
                    float v = s.listD[(tid * 16 + l) * KNN + ptr[l]];
                    if (v < bd) { bd = v; bl = l; }
                }
            }
            s.selW[tid * KNN + o] = bd;
            s.selI[tid * KNN + o] = s.listI[(tid * 16 + bl) * KNN + ptr[bl]];
            ptr[bl]++;
        }
        float d19 = sqrtf(fmaxf(s.selW[tid * KNN + KNN - 1], 1e-30f));
        float h = fmaxf(d19, 1e-12f);
        float inv2h2 = 1.f / (2.f * h * h);
        float wsum = 0.f;
        for (int o = 0; o < KNN; o++) {
            float d = sqrtf(fmaxf(s.selW[tid * KNN + o], 1e-30f));
            float w = expf(-d * d * inv2h2);
            s.selW[tid * KNN + o] = w; wsum += w;
        }
        float inv = 1.f / (wsum + 1e-12f);
        for (int o = 0; o < KNN; o++) s.selW[tid * KNN + o] *= inv;
    }
    __syncthreads();

    // u_t = sum_o w_o * velocity[idx_o]  (16 threads per query, 4 dims each)
    {
        int d0 = pg * 4;
        float u0 = 0.f, u1 = 0.f, u2 = 0.f, u3 = 0.f;
#pragma unroll
        for (int o = 0; o < KNN; o++) {
            float w = s.selW[q * KNN + o];
            int idx = s.selI[q * KNN + o];
            float4 v = *reinterpret_cast<const float4*>(velocity + idx * 64 + d0);
            u0 += w * v.x; u1 += w * v.y; u2 += w * v.z; u3 += w * v.w;
        }
        s.uS[q * 68 + d0 + 0] = u0;
        s.uS[q * 68 + d0 + 1] = u1;
        s.uS[q * 68 + d0 + 2] = u2;
        s.uS[q * 68 + d0 + 3] = u3;
    }
    __syncthreads();

    // cos_sim + L2 metrics
    if (tid < 16) {
        int gq = q0 + tid;
        float dot = 0.f, uu = 0.f, xx = 0.f;
#pragma unroll
        for (int d = 0; d < 64; d++) {
            float uv = s.uS[tid * 68 + d];
            float xv = out[gq * 66 + d];
            dot += uv * xv; uu += uv * uv; xx += xv * xv;
        }
        float nu = fmaxf(sqrtf(uu), 1e-8f);
        float nx = fmaxf(sqrtf(xx), 1e-8f);
        out[gq * 66 + 64] = 1.f - dot / (nu * nx);
        out[gq * 66 + 65] = uu - 2.f * dot + xx;
    }
}

// ---------------------------------------------------------------------------
extern "C" void kernel_launch(void* const* d_in, const int* in_sizes, int n_in,
                              void* d_out, int out_size)
{
    const float* t        = (const float*)d_in[0];
    const float* z        = (const float*)d_in[1];
    const float* data     = (const float*)d_in[2];
    const float* velocity = (const float*)d_in[3];
    const float* W1       = (const float*)d_in[4];
    const float* b1       = (const float*)d_in[5];
    const float* W2       = (const float*)d_in[6];
    const float* b2       = (const float*)d_in[7];
    float* out = (float*)d_out;

    cudaFuncSetAttribute(knn_k, cudaFuncAttributeMaxDynamicSharedMemorySize,
                         (int)sizeof(KSmem));

    dim3 tg(NP / 32, D / 32);
    transpose_k<<<tg, dim3(32, 8)>>>(data);
    pp_k<<<(NP + 255) / 256, 256>>>();
    mlp_k<<<BQ / 16, 256>>>(t, z, W1, b1, W2, b2, out);
    knn_k<<<BQ / QB, 256, sizeof(KSmem)>>>(z, velocity, out);
}

// round 3
// speedup vs baseline: 1.1733x; 1.1733x over previous
#include <cuda_runtime.h>
#include <math.h>

#define N_DATA 100000
#define NP     100096              // padded to 782 * 128
#define N_TILES (NP / 128)
#define NSPLIT 2
#define T2     (N_TILES / NSPLIT)  // 391 tiles per split
#define D      64
#define BQ     2048
#define QB     16                  // queries per CTA
#define KNN    20

__device__ float g_dataT[D * NP];  // transposed data, dim-major
__device__ float g_pp[NP];         // ||p||^2 (1e30 for padding)
__device__ float g_candD[BQ * NSPLIT * KNN];
__device__ int   g_candI[BQ * NSPLIT * KNN];

// ---------------------------------------------------------------------------
__device__ __forceinline__ void cp_async16(void* smem, const void* gmem) {
    unsigned s = (unsigned)__cvta_generic_to_shared(smem);
    asm volatile("cp.async.cg.shared.global [%0], [%1], 16;" :: "r"(s), "l"(gmem));
}
#define CP_COMMIT() asm volatile("cp.async.commit_group;")
#define CP_WAIT1()  asm volatile("cp.async.wait_group 1;")

// ---------------------------------------------------------------------------
// Transpose data (N,64) -> dataT (64, NP), zero-pad tail points
// ---------------------------------------------------------------------------
__global__ void transpose_k(const float* __restrict__ data) {
    __shared__ float t[32][33];
    int p0 = blockIdx.x * 32, j0 = blockIdx.y * 32;
    for (int r = threadIdx.y; r < 32; r += 8) {
        int p = p0 + r;
        t[r][threadIdx.x] = (p < N_DATA) ? data[p * D + j0 + threadIdx.x] : 0.f;
    }
    __syncthreads();
    for (int r = threadIdx.y; r < 32; r += 8) {
        g_dataT[(j0 + r) * NP + p0 + threadIdx.x] = t[threadIdx.x][r];
    }
}

__global__ void pp_k() {
    int p = blockIdx.x * 256 + threadIdx.x;
    if (p >= NP) return;
    if (p >= N_DATA) { g_pp[p] = 1e30f; return; }
    float s = 0.f;
#pragma unroll
    for (int j = 0; j < D; j++) { float v = g_dataT[j * NP + p]; s += v * v; }
    g_pp[p] = s;
}

// ---------------------------------------------------------------------------
// MLP: x_dot = relu([x,t] @ W1 + b1) @ W2 + b2 ; write into out[:, 0:64]
// ---------------------------------------------------------------------------
__global__ __launch_bounds__(256) void mlp_k(
    const float* __restrict__ t, const float* __restrict__ z,
    const float* __restrict__ W1, const float* __restrict__ b1,
    const float* __restrict__ W2, const float* __restrict__ b2,
    float* __restrict__ out)
{
    __shared__ float sIn[16 * 68];
    __shared__ float sH[16 * 258];
    int tid = threadIdx.x;
    int r0 = blockIdx.x * 16;
    float tv = t[0];
    for (int i = tid; i < 16 * 65; i += 256) {
        int r = i / 65, c = i % 65;
        sIn[r * 68 + c] = (c < 64) ? z[(r0 + r) * 66 + c] : tv;
    }
    __syncthreads();
    {
        int r = tid & 15, jb = tid >> 4;
#pragma unroll
        for (int jj = 0; jj < 16; jj++) {
            int j = jb + jj * 16;
            float acc = b1[j];
#pragma unroll
            for (int i = 0; i < 65; i++) acc += sIn[r * 68 + i] * W1[i * 256 + j];
            sH[r * 258 + j] = fmaxf(acc, 0.f);
        }
    }
    __syncthreads();
    {
        int r = tid >> 4, db = tid & 15;
        int d0 = db * 4;
        float a0 = b2[d0], a1 = b2[d0 + 1], a2 = b2[d0 + 2], a3 = b2[d0 + 3];
#pragma unroll 8
        for (int j = 0; j < 256; j++) {
            float hv = sH[r * 258 + j];
            float4 w = *reinterpret_cast<const float4*>(W2 + j * 64 + d0);
            a0 += hv * w.x; a1 += hv * w.y; a2 += hv * w.z; a3 += hv * w.w;
        }
        int gq = r0 + r;
        out[gq * 66 + d0 + 0] = a0;
        out[gq * 66 + d0 + 1] = a1;
        out[gq * 66 + d0 + 2] = a2;
        out[gq * 66 + d0 + 3] = a3;
    }
}

// ---------------------------------------------------------------------------
// KNN over one split of the point range. 256 threads, 16 queries/CTA.
// Double-buffered cp.async tile pipeline; register-resident sorted top-20.
// ---------------------------------------------------------------------------
struct Phase1 {
    float sD[2][64 * 132];   // tile double buffer, dim-major, stride 132
    float ppT[2][128];
    float sQ[64 * 16];       // queries, dim-major
    float qq[16];
};
struct Phase2 {
    float listD[256 * KNN];
    int   listI[256 * KNN];
};
union KSmem { Phase1 p1; Phase2 p2; };

__device__ __forceinline__ void load_tile_async(KSmem& s, int buf, int tile, int tid) {
    const float* gsrc = g_dataT + tile * 128;
#pragma unroll
    for (int i = 0; i < 8; i++) {
        int idx = tid + i * 256;
        int j = idx >> 5, p4 = idx & 31;
        cp_async16(&s.p1.sD[buf][j * 132 + p4 * 4], gsrc + j * NP + p4 * 4);
    }
    if (tid < 32) cp_async16(&s.p1.ppT[buf][tid * 4], g_pp + tile * 128 + tid * 4);
}

__global__ __launch_bounds__(256, 2) void knn_k(const float* __restrict__ z)
{
    extern __shared__ char smem_raw[];
    KSmem& s = *reinterpret_cast<KSmem*>(smem_raw);
    int tid = threadIdx.x;
    int q = tid >> 4, pg = tid & 15;
    int q0 = blockIdx.x * QB;
    int split = blockIdx.y;
    int t0 = split * T2;

    // start prefetch of first two tiles
    load_tile_async(s, 0, t0, tid);
    CP_COMMIT();
    load_tile_async(s, 1, t0 + 1, tid);
    CP_COMMIT();

    // load 16 queries (dim-major) + ||q||^2
    for (int i = tid; i < 64 * 16; i += 256) {
        int qq_ = i & 15, j = i >> 4;
        s.p1.sQ[j * 16 + qq_] = z[(q0 + qq_) * 66 + j];
    }
    __syncthreads();
    if (tid < 16) {
        float sum = 0.f;
#pragma unroll
        for (int j = 0; j < 64; j++) { float v = s.p1.sQ[j * 16 + tid]; sum += v * v; }
        s.p1.qq[tid] = sum;
    }
    __syncthreads();
    float qqv = s.p1.qq[q];

    float best[KNN]; int bestI[KNN];
#pragma unroll
    for (int k = 0; k < KNN; k++) { best[k] = 3.4e38f; bestI[k] = 0; }

    for (int tt = 0; tt < T2; tt++) {
        int buf = tt & 1;
        CP_WAIT1();              // tile tt resident
        __syncthreads();

        float acc[8] = {0.f, 0.f, 0.f, 0.f, 0.f, 0.f, 0.f, 0.f};
        const float* qptr = s.p1.sQ + q;
        const float* dbase = s.p1.sD[buf] + pg * 8;
#pragma unroll 4
        for (int j = 0; j < 64; j++) {
            float qv = qptr[j * 16];
            float4 a  = *reinterpret_cast<const float4*>(dbase + j * 132);
            float4 b4 = *reinterpret_cast<const float4*>(dbase + j * 132 + 4);
            acc[0] += qv * a.x;  acc[1] += qv * a.y;
            acc[2] += qv * a.z;  acc[3] += qv * a.w;
            acc[4] += qv * b4.x; acc[5] += qv * b4.y;
            acc[6] += qv * b4.z; acc[7] += qv * b4.w;
        }
        int pbase = (t0 + tt) * 128 + pg * 8;
#pragma unroll
        for (int i = 0; i < 8; i++) {
            float sq = qqv + s.p1.ppT[buf][pg * 8 + i] - 2.f * acc[i];
            if (sq < best[KNN - 1]) {
                float cd = sq; int ci = pbase + i;
#pragma unroll
                for (int k = 0; k < KNN; k++) {
                    if (cd < best[k]) {
                        float td = best[k]; best[k] = cd; cd = td;
                        int ti = bestI[k]; bestI[k] = ci; ci = ti;
                    }
                }
            }
        }
        __syncthreads();         // all readers done before buf is overwritten
        if (tt + 2 < T2) load_tile_async(s, buf, t0 + tt + 2, tid);
        CP_COMMIT();
    }
    __syncthreads();

    // dump per-thread lists (aliases the tile buffers — safe after sync)
#pragma unroll
    for (int k = 0; k < KNN; k++) {
        s.p2.listD[tid * KNN + k] = best[k];
        s.p2.listI[tid * KNN + k] = bestI[k];
    }
    __syncthreads();

    // 16-way merge per query -> global sorted candidate list (sq distances)
    if (tid < 16) {
        int ptr[16];
#pragma unroll
        for (int l = 0; l < 16; l++) ptr[l] = 0;
        int gbase = (q0 + tid) * (NSPLIT * KNN) + split * KNN;
        for (int o = 0; o < KNN; o++) {
            float bd = 3.5e38f; int bl = 0;
            for (int l = 0; l < 16; l++) {
                if (ptr[l] < KNN) {
                    float v = s.p2.listD[(tid * 16 + l) * KNN + ptr[l]];
                    if (v < bd) { bd = v; bl = l; }
                }
            }
            g_candD[gbase + o] = bd;
            g_candI[gbase + o] = s.p2.listI[(tid * 16 + bl) * KNN + ptr[bl]];
            ptr[bl]++;
        }
    }
}

// ---------------------------------------------------------------------------
// Final: merge per-split candidates, weights, velocity gather, metrics.
// ---------------------------------------------------------------------------
__global__ __launch_bounds__(256) void fin_k(
    const float* __restrict__ velocity, float* __restrict__ out)
{
    __shared__ float selW[16 * KNN];
    __shared__ int   selI[16 * KNN];
    __shared__ float uS[16 * 68];
    int tid = threadIdx.x;
    int q = tid >> 4, pg = tid & 15;
    int q0 = blockIdx.x * 16;

    if (tid < 16) {
        int base = (q0 + tid) * (NSPLIT * KNN);
        int a = 0, b = 0;
        float sd[KNN]; int si[KNN];
        for (int o = 0; o < KNN; o++) {
            float da = g_candD[base + a];
            float db_ = g_candD[base + KNN + b];
            if (da <= db_) { sd[o] = da; si[o] = g_candI[base + a]; a++; }
            else           { sd[o] = db_; si[o] = g_candI[base + KNN + b]; b++; }
        }
        float d19 = sqrtf(fmaxf(sd[KNN - 1], 1e-30f));
        float h = fmaxf(d19, 1e-12f);
        float inv2h2 = 1.f / (2.f * h * h);
        float wsum = 0.f;
        float w[KNN];
#pragma unroll
        for (int o = 0; o < KNN; o++) {
            float d = sqrtf(fmaxf(sd[o], 1e-30f));
            w[o] = expf(-d * d * inv2h2);
            wsum += w[o];
        }
        float inv = 1.f / (wsum + 1e-12f);
#pragma unroll
        for (int o = 0; o < KNN; o++) {
            selW[tid * KNN + o] = w[o] * inv;
            selI[tid * KNN + o] = si[o];
        }
    }
    __syncthreads();

    {
        int d0 = pg * 4;
        float u0 = 0.f, u1 = 0.f, u2 = 0.f, u3 = 0.f;
#pragma unroll
        for (int o = 0; o < KNN; o++) {
            float w = selW[q * KNN + o];
            int idx = selI[q * KNN + o];
            float4 v = *reinterpret_cast<const float4*>(velocity + idx * 64 + d0);
            u0 += w * v.x; u1 += w * v.y; u2 += w * v.z; u3 += w * v.w;
        }
        uS[q * 68 + d0 + 0] = u0;
        uS[q * 68 + d0 + 1] = u1;
        uS[q * 68 + d0 + 2] = u2;
        uS[q * 68 + d0 + 3] = u3;
    }
    __syncthreads();

    if (tid < 16) {
        int gq = q0 + tid;
        float dot = 0.f, uu = 0.f, xx = 0.f;
#pragma unroll
        for (int d = 0; d < 64; d++) {
            float uv = uS[tid * 68 + d];
            float xv = out[gq * 66 + d];
            dot += uv * xv; uu += uv * uv; xx += xv * xv;
        }
        float nu = fmaxf(sqrtf(uu), 1e-8f);
        float nx = fmaxf(sqrtf(xx), 1e-8f);
        out[gq * 66 + 64] = 1.f - dot / (nu * nx);
        out[gq * 66 + 65] = uu - 2.f * dot + xx;
    }
}

// ---------------------------------------------------------------------------
extern "C" void kernel_launch(void* const* d_in, const int* in_sizes, int n_in,
                              void* d_out, int out_size)
{
    const float* t        = (const float*)d_in[0];
    const float* z        = (const float*)d_in[1];
    const float* data     = (const float*)d_in[2];
    const float* velocity = (const float*)d_in[3];
    const float* W1       = (const float*)d_in[4];
    const float* b1       = (const float*)d_in[5];
    const float* W2       = (const float*)d_in[6];
    const float* b2       = (const float*)d_in[7];
    float* out = (float*)d_out;

    static int attr_set = 0;
    if (!attr_set) {
        cudaFuncSetAttribute(knn_k, cudaFuncAttributeMaxDynamicSharedMemorySize,
                             (int)sizeof(KSmem));
        attr_set = 1;
    }

    dim3 tg(NP / 32, D / 32);
    transpose_k<<<tg, dim3(32, 8)>>>(data);
    pp_k<<<(NP + 255) / 256, 256>>>();
    mlp_k<<<BQ / 16, 256>>>(t, z, W1, b1, W2, b2, out);
    knn_k<<<dim3(BQ / QB, NSPLIT), 256, sizeof(KSmem)>>>(z);
    fin_k<<<BQ / 16, 256>>>(velocity, out);
}